// round 13
// baseline (speedup 1.0000x reference)
#include <cuda_runtime.h>
#include <cuda_bf16.h>

#define NA 8192
#define NP 65536
#define FDIM 128
#define RD 20
#define NB 5
#define TMX 8

// Scratch (allocation-free rule: __device__ globals; zero-initialized at load)
__device__ __align__(16) float g_x[NA * 384];
__device__ __align__(16) float g_dq[NA * FDIM];    // invariant: zero at launch entry
__device__ __align__(16) float g_dmu[NA * 384];    // invariant: zero at launch entry

__device__ __forceinline__ float silu(float z) { return z / (1.f + __expf(-z)); }

__device__ __forceinline__ void red4(float* p, float a, float b, float c, float d) {
    asm volatile("red.global.add.v4.f32 [%0], {%1,%2,%3,%4};"
                 :: "l"(p), "f"(a), "f"(b), "f"(c), "f"(d) : "memory");
}

// ---------------------------------------------------------------------------
// k_x (R7-proven): x = silu(q @ W1 + b1) @ W2 + b2. 8 atoms/CTA, 128 thr.
// Used only for block 0 (initial q = features).
// ---------------------------------------------------------------------------
__global__ void __launch_bounds__(128) k_x(
    const float* __restrict__ q,
    const float* __restrict__ W1, const float* __restrict__ b1,
    const float* __restrict__ W2, const float* __restrict__ b2,
    float* __restrict__ x)
{
    __shared__ __align__(16) float qs[TMX * FDIM];
    __shared__ __align__(16) float hs[TMX * FDIM];
    const int tid = threadIdx.x;
    const int atom0 = blockIdx.x * TMX;
    const int f = tid;

    {
        const float4* src = (const float4*)(q + atom0 * FDIM);
        float4* dst = (float4*)qs;
        for (int c = tid; c < TMX * 32; c += 128) dst[c] = src[c];
    }
    __syncthreads();

    const float4* qs4 = (const float4*)qs;
    {
        float acc[TMX];
#pragma unroll
        for (int a = 0; a < TMX; a++) acc[a] = 0.f;
#pragma unroll 2
        for (int kp = 0; kp < 32; kp++) {
            const float w0 = W1[(4 * kp)     * FDIM + f];
            const float w1 = W1[(4 * kp + 1) * FDIM + f];
            const float w2 = W1[(4 * kp + 2) * FDIM + f];
            const float w3 = W1[(4 * kp + 3) * FDIM + f];
#pragma unroll
            for (int a = 0; a < TMX; a++) {
                const float4 v = qs4[a * 32 + kp];
                acc[a] += v.x * w0 + v.y * w1 + v.z * w2 + v.w * w3;
            }
        }
        const float bb = b1[f];
#pragma unroll
        for (int a = 0; a < TMX; a++) hs[a * FDIM + f] = silu(acc[a] + bb);
    }
    __syncthreads();

    {
        const float4* hs4 = (const float4*)hs;
        float accA[TMX], accB[TMX], accC[TMX];
#pragma unroll
        for (int a = 0; a < TMX; a++) { accA[a] = 0.f; accB[a] = 0.f; accC[a] = 0.f; }
#pragma unroll 2
        for (int kp = 0; kp < 32; kp++) {
            float wa[4], wb[4], wc[4];
#pragma unroll
            for (int t = 0; t < 4; t++) {
                wa[t] = W2[(4 * kp + t) * 384 + f];
                wb[t] = W2[(4 * kp + t) * 384 + FDIM + f];
                wc[t] = W2[(4 * kp + t) * 384 + 2 * FDIM + f];
            }
#pragma unroll
            for (int a = 0; a < TMX; a++) {
                const float4 v = hs4[a * 32 + kp];
                accA[a] += v.x * wa[0] + v.y * wa[1] + v.z * wa[2] + v.w * wa[3];
                accB[a] += v.x * wb[0] + v.y * wb[1] + v.z * wb[2] + v.w * wb[3];
                accC[a] += v.x * wc[0] + v.y * wc[1] + v.z * wc[2] + v.w * wc[3];
            }
        }
        const float bA = b2[f], bB = b2[FDIM + f], bC = b2[2 * FDIM + f];
#pragma unroll
        for (int a = 0; a < TMX; a++) {
            x[(atom0 + a) * 384 + f]            = accA[a] + bA;
            x[(atom0 + a) * 384 + FDIM + f]     = accB[a] + bB;
            x[(atom0 + a) * 384 + 2 * FDIM + f] = accC[a] + bC;
        }
    }
}

// ---------------------------------------------------------------------------
// k_pairs (R12-proven): fused filter + gather + RED scatter, 4 pairs/warp.
// ---------------------------------------------------------------------------
__global__ void __launch_bounds__(128) k_pairs(
    const float* __restrict__ x, const float* __restrict__ mu,
    const float* __restrict__ dist, const float* __restrict__ vec,
    const float* __restrict__ cut, const float* __restrict__ rbf,
    const float* __restrict__ fW,   // pre-offset by b*384, row stride 1920
    const float* __restrict__ fb,   // pre-offset by b*384
    const int* __restrict__ idx_i, const int* __restrict__ idx_j,
    float* __restrict__ dq, float* __restrict__ dmu)
{
    __shared__ __align__(16) float fw_s[RD * 384];
    __shared__ __align__(16) float fb_s[384];
    const int tid = threadIdx.x;
    for (int c = tid; c < RD * 384; c += 128) {
        int r = c / 384, cc = c - r * 384;
        fw_s[c] = fW[r * 1920 + cc];
    }
    for (int c = tid; c < 384; c += 128) fb_s[c] = fb[c];
    __syncthreads();

    const int lane = tid & 31;
    const int gw = blockIdx.x * 4 + (tid >> 5);
    const int nw = gridDim.x * 4;
    const float4* fw4 = (const float4*)fw_s;   // [RD][96]
    const float4* fb4 = (const float4*)fb_s;   // [96]
    const float4* X4 = (const float4*)x;       // [NA][96]
    const float4* M4 = (const float4*)mu;      // [NA*3][32]

    const float4 fbq = fb4[lane];
    const float4 fbr = fb4[32 + lane];
    const float4 fbm = fb4[64 + lane];

    for (int g = gw; g < NP / 4; g += nw) {
        const int pbase = g * 4;

        int ii[4], jj[4];
        float cu[4], e0[4], e1[4], e2[4];
#pragma unroll
        for (int pp = 0; pp < 4; pp++) {
            const int p = pbase + pp;
            ii[pp] = idx_i[p];
            jj[pp] = idx_j[p];
            const float dinv = 1.f / dist[p];
            cu[pp] = cut[p];
            e0[pp] = vec[3 * p] * dinv;
            e1[pp] = vec[3 * p + 1] * dinv;
            e2[pp] = vec[3 * p + 2] * dinv;
        }

        float4 wq[4], wr[4], wm[4];
#pragma unroll
        for (int pp = 0; pp < 4; pp++) {
            wq[pp] = make_float4(0.f, 0.f, 0.f, 0.f);
            wr[pp] = wq[pp]; wm[pp] = wq[pp];
        }
#pragma unroll 4
        for (int r = 0; r < RD; r++) {
            const float4 t0 = fw4[r * 96 + lane];
            const float4 t1 = fw4[r * 96 + 32 + lane];
            const float4 t2 = fw4[r * 96 + 64 + lane];
#pragma unroll
            for (int pp = 0; pp < 4; pp++) {
                const float rb = rbf[(pbase + pp) * RD + r];
                wq[pp].x += rb * t0.x; wq[pp].y += rb * t0.y;
                wq[pp].z += rb * t0.z; wq[pp].w += rb * t0.w;
                wr[pp].x += rb * t1.x; wr[pp].y += rb * t1.y;
                wr[pp].z += rb * t1.z; wr[pp].w += rb * t1.w;
                wm[pp].x += rb * t2.x; wm[pp].y += rb * t2.y;
                wm[pp].z += rb * t2.z; wm[pp].w += rb * t2.w;
            }
        }

#pragma unroll
        for (int pp = 0; pp < 4; pp++) {
            const int i = ii[pp];
            const int j = jj[pp];
            const float c = cu[pp];
            const float4 WQ = make_float4((wq[pp].x + fbq.x) * c, (wq[pp].y + fbq.y) * c,
                                          (wq[pp].z + fbq.z) * c, (wq[pp].w + fbq.w) * c);
            const float4 WR = make_float4((wr[pp].x + fbr.x) * c, (wr[pp].y + fbr.y) * c,
                                          (wr[pp].z + fbr.z) * c, (wr[pp].w + fbr.w) * c);
            const float4 WM = make_float4((wm[pp].x + fbm.x) * c, (wm[pp].y + fbm.y) * c,
                                          (wm[pp].z + fbm.z) * c, (wm[pp].w + fbm.w) * c);

            const float4 xq = X4[j * 96 + lane];
            const float4 xr = X4[j * 96 + 32 + lane];
            const float4 xm = X4[j * 96 + 64 + lane];

            red4(dq + i * FDIM + lane * 4,
                 xq.x * WQ.x, xq.y * WQ.y, xq.z * WQ.z, xq.w * WQ.w);

            const float ax = xr.x * WR.x, ay = xr.y * WR.y, az = xr.z * WR.z, aw = xr.w * WR.w;
            const float cx = xm.x * WM.x, cy = xm.y * WM.y, cz = xm.z * WM.z, cw = xm.w * WM.w;

            const float d0 = e0[pp], d1 = e1[pp], d2 = e2[pp];
            const float4 mj0 = M4[(j * 3 + 0) * 32 + lane];
            red4(dmu + (i * 3 + 0) * FDIM + lane * 4,
                 ax * d0 + cx * mj0.x, ay * d0 + cy * mj0.y,
                 az * d0 + cz * mj0.z, aw * d0 + cw * mj0.w);
            const float4 mj1 = M4[(j * 3 + 1) * 32 + lane];
            red4(dmu + (i * 3 + 1) * FDIM + lane * 4,
                 ax * d1 + cx * mj1.x, ay * d1 + cy * mj1.y,
                 az * d1 + cz * mj1.z, aw * d1 + cw * mj1.w);
            const float4 mj2 = M4[(j * 3 + 2) * 32 + lane];
            red4(dmu + (i * 3 + 2) * FDIM + lane * 4,
                 ax * d2 + cx * mj2.x, ay * d2 + cy * mj2.y,
                 az * d2 + cz * mj2.z, aw * d2 + cw * mj2.w);
        }
    }
}

// ---------------------------------------------------------------------------
// k_mixx: k_mix (R7-proven structure) + fused next-block x-MLP.
// Fold phase ALSO zeroes dq/dmu (restores the zero invariant, replacing
// memsets). If do_x != 0, after the gated update the new q (already in qs
// smem) feeds x = silu(q @ xW1 + xb1) @ xW2 + xb2 for the next block.
// ---------------------------------------------------------------------------
__global__ void __launch_bounds__(128) k_mixx(
    float* __restrict__ q, float* __restrict__ mu,
    float* __restrict__ dq, float* __restrict__ dmu,
    const float* __restrict__ Wv,                                  // [128][256]
    const float* __restrict__ mW1, const float* __restrict__ mb1,  // [256][128]
    const float* __restrict__ mW2, const float* __restrict__ mb2,  // [128][384]
    const float* __restrict__ xW1, const float* __restrict__ xb1,  // next block
    const float* __restrict__ xW2, const float* __restrict__ xb2,
    float* __restrict__ x, int do_x)
{
    __shared__ __align__(16) float qs[TMX * FDIM];
    __shared__ __align__(16) float mus[TMX * 384];
    __shared__ __align__(16) float mws[TMX * 384];
    __shared__ __align__(16) float ns[TMX * FDIM];
    __shared__ __align__(16) float hs[TMX * FDIM];

    const int tid = threadIdx.x;
    const int atom0 = blockIdx.x * TMX;
    const int f = tid;

    // fold segment sums into smem; zero dq/dmu behind us
    {
        const float4 z4 = make_float4(0.f, 0.f, 0.f, 0.f);
        const float4* sq = (const float4*)(q + atom0 * FDIM);
        float4* sdq = (float4*)(dq + atom0 * FDIM);
        float4* dst = (float4*)qs;
        for (int c = tid; c < TMX * 32; c += 128) {
            float4 a = sq[c], b = sdq[c];
            dst[c] = make_float4(a.x + b.x, a.y + b.y, a.z + b.z, a.w + b.w);
            sdq[c] = z4;
        }
        const float4* sm = (const float4*)(mu + atom0 * 384);
        float4* sdm = (float4*)(dmu + atom0 * 384);
        float4* dstm = (float4*)mus;
        for (int c = tid; c < TMX * 96; c += 128) {
            float4 a = sm[c], b = sdm[c];
            dstm[c] = make_float4(a.x + b.x, a.y + b.y, a.z + b.z, a.w + b.w);
            sdm[c] = z4;
        }
    }
    __syncthreads();

    const float4* mus4 = (const float4*)mus;
    float nsq[TMX], dot[TMX];
#pragma unroll
    for (int a = 0; a < TMX; a++) { nsq[a] = 0.f; dot[a] = 0.f; }

#pragma unroll 1
    for (int d = 0; d < 3; d++) {
        float accV[TMX], accW[TMX];
#pragma unroll
        for (int a = 0; a < TMX; a++) { accV[a] = 0.f; accW[a] = 0.f; }
#pragma unroll 2
        for (int kp = 0; kp < 32; kp++) {
            float wv[4], ww[4];
#pragma unroll
            for (int t = 0; t < 4; t++) {
                wv[t] = Wv[(4 * kp + t) * 256 + f];
                ww[t] = Wv[(4 * kp + t) * 256 + FDIM + f];
            }
#pragma unroll
            for (int a = 0; a < TMX; a++) {
                const float4 m = mus4[a * 96 + d * 32 + kp];
                accV[a] += m.x * wv[0] + m.y * wv[1] + m.z * wv[2] + m.w * wv[3];
                accW[a] += m.x * ww[0] + m.y * ww[1] + m.z * ww[2] + m.w * ww[3];
            }
        }
#pragma unroll
        for (int a = 0; a < TMX; a++) {
            mws[a * 384 + d * FDIM + f] = accW[a];
            nsq[a] += accV[a] * accV[a];
            dot[a] += accV[a] * accW[a];
        }
    }
#pragma unroll
    for (int a = 0; a < TMX; a++) ns[a * FDIM + f] = sqrtf(nsq[a] + 1e-8f);
    __syncthreads();

    // h = silu(ctx @ mW1 + mb1), ctx = [q | ||mu_V||]
    {
        const float4* qs4 = (const float4*)qs;
        const float4* ns4 = (const float4*)ns;
        float acc[TMX];
#pragma unroll
        for (int a = 0; a < TMX; a++) acc[a] = 0.f;
#pragma unroll 2
        for (int kp = 0; kp < 32; kp++) {
            float w[4];
#pragma unroll
            for (int t = 0; t < 4; t++) w[t] = mW1[(4 * kp + t) * FDIM + f];
#pragma unroll
            for (int a = 0; a < TMX; a++) {
                const float4 v = qs4[a * 32 + kp];
                acc[a] += v.x * w[0] + v.y * w[1] + v.z * w[2] + v.w * w[3];
            }
        }
#pragma unroll 2
        for (int kp = 0; kp < 32; kp++) {
            float w[4];
#pragma unroll
            for (int t = 0; t < 4; t++) w[t] = mW1[(FDIM + 4 * kp + t) * FDIM + f];
#pragma unroll
            for (int a = 0; a < TMX; a++) {
                const float4 v = ns4[a * 32 + kp];
                acc[a] += v.x * w[0] + v.y * w[1] + v.z * w[2] + v.w * w[3];
            }
        }
        const float bb = mb1[f];
#pragma unroll
        for (int a = 0; a < TMX; a++) hs[a * FDIM + f] = silu(acc[a] + bb);
    }
    __syncthreads();

    // y = h @ mW2 + mb2; gated update; new q -> global AND qs (in place)
    {
        const float4* hs4 = (const float4*)hs;
        float accA[TMX], accB[TMX], accC[TMX];
#pragma unroll
        for (int a = 0; a < TMX; a++) { accA[a] = 0.f; accB[a] = 0.f; accC[a] = 0.f; }
#pragma unroll 2
        for (int kp = 0; kp < 32; kp++) {
            float wa[4], wb[4], wc[4];
#pragma unroll
            for (int t = 0; t < 4; t++) {
                wa[t] = mW2[(4 * kp + t) * 384 + f];
                wb[t] = mW2[(4 * kp + t) * 384 + FDIM + f];
                wc[t] = mW2[(4 * kp + t) * 384 + 2 * FDIM + f];
            }
#pragma unroll
            for (int a = 0; a < TMX; a++) {
                const float4 v = hs4[a * 32 + kp];
                accA[a] += v.x * wa[0] + v.y * wa[1] + v.z * wa[2] + v.w * wa[3];
                accB[a] += v.x * wb[0] + v.y * wb[1] + v.z * wb[2] + v.w * wb[3];
                accC[a] += v.x * wc[0] + v.y * wc[1] + v.z * wc[2] + v.w * wc[3];
            }
        }
        const float bA = mb2[f], bB = mb2[FDIM + f], bC = mb2[2 * FDIM + f];
#pragma unroll
        for (int a = 0; a < TMX; a++) {
            const float yA = accA[a] + bA;
            const float yB = accB[a] + bB;
            const float yC = accC[a] + bC;
            const float nq = qs[a * FDIM + f] + yA + yC * dot[a];
            q[(atom0 + a) * FDIM + f] = nq;
            qs[a * FDIM + f] = nq;          // same thread owns this slot
#pragma unroll
            for (int d = 0; d < 3; d++)
                mu[(atom0 + a) * 384 + d * FDIM + f] =
                    mus[a * 384 + d * FDIM + f] + yB * mws[a * 384 + d * FDIM + f];
        }
    }

    if (!do_x) return;
    __syncthreads();

    // Next block's x-MLP on the new q (in qs)
    const float4* qs4 = (const float4*)qs;
    {
        float acc[TMX];
#pragma unroll
        for (int a = 0; a < TMX; a++) acc[a] = 0.f;
#pragma unroll 2
        for (int kp = 0; kp < 32; kp++) {
            const float w0 = xW1[(4 * kp)     * FDIM + f];
            const float w1 = xW1[(4 * kp + 1) * FDIM + f];
            const float w2 = xW1[(4 * kp + 2) * FDIM + f];
            const float w3 = xW1[(4 * kp + 3) * FDIM + f];
#pragma unroll
            for (int a = 0; a < TMX; a++) {
                const float4 v = qs4[a * 32 + kp];
                acc[a] += v.x * w0 + v.y * w1 + v.z * w2 + v.w * w3;
            }
        }
        const float bb = xb1[f];
#pragma unroll
        for (int a = 0; a < TMX; a++) hs[a * FDIM + f] = silu(acc[a] + bb);
    }
    __syncthreads();

    {
        const float4* hs4 = (const float4*)hs;
        float accA[TMX], accB[TMX], accC[TMX];
#pragma unroll
        for (int a = 0; a < TMX; a++) { accA[a] = 0.f; accB[a] = 0.f; accC[a] = 0.f; }
#pragma unroll 2
        for (int kp = 0; kp < 32; kp++) {
            float wa[4], wb[4], wc[4];
#pragma unroll
            for (int t = 0; t < 4; t++) {
                wa[t] = xW2[(4 * kp + t) * 384 + f];
                wb[t] = xW2[(4 * kp + t) * 384 + FDIM + f];
                wc[t] = xW2[(4 * kp + t) * 384 + 2 * FDIM + f];
            }
#pragma unroll
            for (int a = 0; a < TMX; a++) {
                const float4 v = hs4[a * 32 + kp];
                accA[a] += v.x * wa[0] + v.y * wa[1] + v.z * wa[2] + v.w * wa[3];
                accB[a] += v.x * wb[0] + v.y * wb[1] + v.z * wb[2] + v.w * wb[3];
                accC[a] += v.x * wc[0] + v.y * wc[1] + v.z * wc[2] + v.w * wc[3];
            }
        }
        const float bA = xb2[f], bB = xb2[FDIM + f], bC = xb2[2 * FDIM + f];
#pragma unroll
        for (int a = 0; a < TMX; a++) {
            x[(atom0 + a) * 384 + f]            = accA[a] + bA;
            x[(atom0 + a) * 384 + FDIM + f]     = accB[a] + bB;
            x[(atom0 + a) * 384 + 2 * FDIM + f] = accC[a] + bC;
        }
    }
}

// ---------------------------------------------------------------------------
extern "C" void kernel_launch(void* const* d_in, const int* in_sizes, int n_in,
                              void* d_out, int out_size)
{
    const float* features = (const float*)d_in[0];
    const float* distances = (const float*)d_in[1];
    const float* vectors = (const float*)d_in[2];
    const float* cutoffs = (const float*)d_in[3];
    const float* rbfs = (const float*)d_in[4];
    const float* filter_W = (const float*)d_in[5];
    const float* filter_b = (const float*)d_in[6];
    const float* int_W1 = (const float*)d_in[7];
    const float* int_b1 = (const float*)d_in[8];
    const float* int_W2 = (const float*)d_in[9];
    const float* int_b2 = (const float*)d_in[10];
    const float* mix_Wv = (const float*)d_in[11];
    const float* mix_W1 = (const float*)d_in[12];
    const float* mix_b1 = (const float*)d_in[13];
    const float* mix_W2 = (const float*)d_in[14];
    const float* mix_b2 = (const float*)d_in[15];
    const int* idx_i = (const int*)d_in[16];
    const int* idx_j = (const int*)d_in[17];

    float* q = (float*)d_out;            // [NA,128]
    float* mu = q + NA * FDIM;           // [NA,3,128]

    float *xbuf, *dqbuf, *dmubuf;
    cudaGetSymbolAddress((void**)&xbuf, g_x);
    cudaGetSymbolAddress((void**)&dqbuf, g_dq);
    cudaGetSymbolAddress((void**)&dmubuf, g_dmu);

    cudaMemcpyAsync(q, features, NA * FDIM * sizeof(float), cudaMemcpyDeviceToDevice);
    cudaMemsetAsync(mu, 0, NA * 384 * sizeof(float));

    // Block 0's x from initial q
    k_x<<<NA / TMX, 128>>>(q, int_W1, int_b1, int_W2, int_b2, xbuf);

    for (int b = 0; b < NB; b++) {
        k_pairs<<<2048, 128>>>(xbuf, mu, distances, vectors, cutoffs, rbfs,
                               filter_W + b * 384, filter_b + b * 384,
                               idx_i, idx_j, dqbuf, dmubuf);
        const int nb = (b < NB - 1) ? b + 1 : b;   // next block's x-weights (dummy on last)
        k_mixx<<<NA / TMX, 128>>>(q, mu, dqbuf, dmubuf,
                                  mix_Wv + b * FDIM * 256,
                                  mix_W1 + b * 256 * FDIM, mix_b1 + b * FDIM,
                                  mix_W2 + b * FDIM * 384, mix_b2 + b * 384,
                                  int_W1 + nb * FDIM * FDIM, int_b1 + nb * FDIM,
                                  int_W2 + nb * FDIM * 384, int_b2 + nb * 384,
                                  xbuf, (b < NB - 1) ? 1 : 0);
    }
}

// round 16
// speedup vs baseline: 1.0202x; 1.0202x over previous
#include <cuda_runtime.h>
#include <cuda_bf16.h>

#define NA 8192
#define NP 65536
#define FDIM 128
#define RD 20
#define NB 5
#define TMX 8

// Scratch (allocation-free rule: __device__ globals; zero-initialized at load)
__device__ __align__(16) float g_x[NA * 384];
__device__ __align__(16) float g_dq[NA * FDIM];    // invariant: zero at launch entry
__device__ __align__(16) float g_dmu[NA * 384];    // invariant: zero at launch entry

__device__ __forceinline__ float silu(float z) { return z / (1.f + __expf(-z)); }

__device__ __forceinline__ void red4(float* p, float a, float b, float c, float d) {
    asm volatile("red.global.add.v4.f32 [%0], {%1,%2,%3,%4};"
                 :: "l"(p), "f"(a), "f"(b), "f"(c), "f"(d) : "memory");
}

// ---------------------------------------------------------------------------
// k_x (R7-proven): x = silu(q @ W1 + b1) @ W2 + b2. 8 atoms/CTA, 128 thr.
// ---------------------------------------------------------------------------
__global__ void __launch_bounds__(128) k_x(
    const float* __restrict__ q,
    const float* __restrict__ W1, const float* __restrict__ b1,
    const float* __restrict__ W2, const float* __restrict__ b2,
    float* __restrict__ x)
{
    __shared__ __align__(16) float qs[TMX * FDIM];
    __shared__ __align__(16) float hs[TMX * FDIM];
    const int tid = threadIdx.x;
    const int atom0 = blockIdx.x * TMX;
    const int f = tid;

    {
        const float4* src = (const float4*)(q + atom0 * FDIM);
        float4* dst = (float4*)qs;
        for (int c = tid; c < TMX * 32; c += 128) dst[c] = src[c];
    }
    __syncthreads();

    const float4* qs4 = (const float4*)qs;
    {
        float acc[TMX];
#pragma unroll
        for (int a = 0; a < TMX; a++) acc[a] = 0.f;
#pragma unroll 2
        for (int kp = 0; kp < 32; kp++) {
            const float w0 = W1[(4 * kp)     * FDIM + f];
            const float w1 = W1[(4 * kp + 1) * FDIM + f];
            const float w2 = W1[(4 * kp + 2) * FDIM + f];
            const float w3 = W1[(4 * kp + 3) * FDIM + f];
#pragma unroll
            for (int a = 0; a < TMX; a++) {
                const float4 v = qs4[a * 32 + kp];
                acc[a] += v.x * w0 + v.y * w1 + v.z * w2 + v.w * w3;
            }
        }
        const float bb = b1[f];
#pragma unroll
        for (int a = 0; a < TMX; a++) hs[a * FDIM + f] = silu(acc[a] + bb);
    }
    __syncthreads();

    {
        const float4* hs4 = (const float4*)hs;
        float accA[TMX], accB[TMX], accC[TMX];
#pragma unroll
        for (int a = 0; a < TMX; a++) { accA[a] = 0.f; accB[a] = 0.f; accC[a] = 0.f; }
#pragma unroll 2
        for (int kp = 0; kp < 32; kp++) {
            float wa[4], wb[4], wc[4];
#pragma unroll
            for (int t = 0; t < 4; t++) {
                wa[t] = W2[(4 * kp + t) * 384 + f];
                wb[t] = W2[(4 * kp + t) * 384 + FDIM + f];
                wc[t] = W2[(4 * kp + t) * 384 + 2 * FDIM + f];
            }
#pragma unroll
            for (int a = 0; a < TMX; a++) {
                const float4 v = hs4[a * 32 + kp];
                accA[a] += v.x * wa[0] + v.y * wa[1] + v.z * wa[2] + v.w * wa[3];
                accB[a] += v.x * wb[0] + v.y * wb[1] + v.z * wb[2] + v.w * wb[3];
                accC[a] += v.x * wc[0] + v.y * wc[1] + v.z * wc[2] + v.w * wc[3];
            }
        }
        const float bA = b2[f], bB = b2[FDIM + f], bC = b2[2 * FDIM + f];
#pragma unroll
        for (int a = 0; a < TMX; a++) {
            x[(atom0 + a) * 384 + f]            = accA[a] + bA;
            x[(atom0 + a) * 384 + FDIM + f]     = accB[a] + bB;
            x[(atom0 + a) * 384 + 2 * FDIM + f] = accC[a] + bC;
        }
    }
}

// ---------------------------------------------------------------------------
// k_pairs: fused filter + gather + RED scatter, 4 pairs/warp.
// Filter sweep carries ONLY the 48 accumulator regs + one rbf float4 chunk
// per pair (geometry/index loads deferred to the epilogue); rbf loaded as
// float4 (5 LDG/pair instead of 20).
// ---------------------------------------------------------------------------
__global__ void __launch_bounds__(128) k_pairs(
    const float* __restrict__ x, const float* __restrict__ mu,
    const float* __restrict__ dist, const float* __restrict__ vec,
    const float* __restrict__ cut, const float* __restrict__ rbf,
    const float* __restrict__ fW,   // pre-offset by b*384, row stride 1920
    const float* __restrict__ fb,   // pre-offset by b*384
    const int* __restrict__ idx_i, const int* __restrict__ idx_j,
    float* __restrict__ dq, float* __restrict__ dmu)
{
    __shared__ __align__(16) float fw_s[RD * 384];
    __shared__ __align__(16) float fb_s[384];
    const int tid = threadIdx.x;
    for (int c = tid; c < RD * 384; c += 128) {
        int r = c / 384, cc = c - r * 384;
        fw_s[c] = fW[r * 1920 + cc];
    }
    for (int c = tid; c < 384; c += 128) fb_s[c] = fb[c];
    __syncthreads();

    const int lane = tid & 31;
    const int gw = blockIdx.x * 4 + (tid >> 5);
    const int nw = gridDim.x * 4;
    const float4* fw4 = (const float4*)fw_s;   // [RD][96]
    const float4* fb4 = (const float4*)fb_s;   // [96]
    const float4* X4 = (const float4*)x;       // [NA][96]
    const float4* M4 = (const float4*)mu;      // [NA*3][32]
    const float4* R4 = (const float4*)rbf;     // [NP][5]

    for (int g = gw; g < NP / 4; g += nw) {
        const int pbase = g * 4;

        // ---- filter sweep: minimal live state ----
        float4 wq[4], wr[4], wm[4];
#pragma unroll
        for (int pp = 0; pp < 4; pp++) {
            wq[pp] = make_float4(0.f, 0.f, 0.f, 0.f);
            wr[pp] = wq[pp]; wm[pp] = wq[pp];
        }
#pragma unroll
        for (int rc = 0; rc < 5; rc++) {
            float4 rb4[4];
#pragma unroll
            for (int pp = 0; pp < 4; pp++)
                rb4[pp] = R4[(pbase + pp) * 5 + rc];
#pragma unroll
            for (int t = 0; t < 4; t++) {
                const int r = rc * 4 + t;
                const float4 t0 = fw4[r * 96 + lane];
                const float4 t1 = fw4[r * 96 + 32 + lane];
                const float4 t2 = fw4[r * 96 + 64 + lane];
#pragma unroll
                for (int pp = 0; pp < 4; pp++) {
                    const float rb = (t == 0) ? rb4[pp].x : (t == 1) ? rb4[pp].y
                                   : (t == 2) ? rb4[pp].z : rb4[pp].w;
                    wq[pp].x += rb * t0.x; wq[pp].y += rb * t0.y;
                    wq[pp].z += rb * t0.z; wq[pp].w += rb * t0.w;
                    wr[pp].x += rb * t1.x; wr[pp].y += rb * t1.y;
                    wr[pp].z += rb * t1.z; wr[pp].w += rb * t1.w;
                    wm[pp].x += rb * t2.x; wm[pp].y += rb * t2.y;
                    wm[pp].z += rb * t2.z; wm[pp].w += rb * t2.w;
                }
            }
        }

        const float4 fbq = fb4[lane];
        const float4 fbr = fb4[32 + lane];
        const float4 fbm = fb4[64 + lane];

        // ---- epilogue: per-pair geometry, gathers, RED scatter ----
#pragma unroll
        for (int pp = 0; pp < 4; pp++) {
            const int p = pbase + pp;
            const int i = idx_i[p];
            const int j = idx_j[p];
            const float c = cut[p];
            const float dinv = 1.f / dist[p];
            const float d0 = vec[3 * p] * dinv;
            const float d1 = vec[3 * p + 1] * dinv;
            const float d2 = vec[3 * p + 2] * dinv;

            const float4 WQ = make_float4((wq[pp].x + fbq.x) * c, (wq[pp].y + fbq.y) * c,
                                          (wq[pp].z + fbq.z) * c, (wq[pp].w + fbq.w) * c);
            const float4 WR = make_float4((wr[pp].x + fbr.x) * c, (wr[pp].y + fbr.y) * c,
                                          (wr[pp].z + fbr.z) * c, (wr[pp].w + fbr.w) * c);
            const float4 WM = make_float4((wm[pp].x + fbm.x) * c, (wm[pp].y + fbm.y) * c,
                                          (wm[pp].z + fbm.z) * c, (wm[pp].w + fbm.w) * c);

            const float4 xq = X4[j * 96 + lane];
            const float4 xr = X4[j * 96 + 32 + lane];
            const float4 xm = X4[j * 96 + 64 + lane];

            red4(dq + i * FDIM + lane * 4,
                 xq.x * WQ.x, xq.y * WQ.y, xq.z * WQ.z, xq.w * WQ.w);

            const float ax = xr.x * WR.x, ay = xr.y * WR.y, az = xr.z * WR.z, aw = xr.w * WR.w;
            const float cx = xm.x * WM.x, cy = xm.y * WM.y, cz = xm.z * WM.z, cw = xm.w * WM.w;

            const float4 mj0 = M4[(j * 3 + 0) * 32 + lane];
            red4(dmu + (i * 3 + 0) * FDIM + lane * 4,
                 ax * d0 + cx * mj0.x, ay * d0 + cy * mj0.y,
                 az * d0 + cz * mj0.z, aw * d0 + cw * mj0.w);
            const float4 mj1 = M4[(j * 3 + 1) * 32 + lane];
            red4(dmu + (i * 3 + 1) * FDIM + lane * 4,
                 ax * d1 + cx * mj1.x, ay * d1 + cy * mj1.y,
                 az * d1 + cz * mj1.z, aw * d1 + cw * mj1.w);
            const float4 mj2 = M4[(j * 3 + 2) * 32 + lane];
            red4(dmu + (i * 3 + 2) * FDIM + lane * 4,
                 ax * d2 + cx * mj2.x, ay * d2 + cy * mj2.y,
                 az * d2 + cz * mj2.z, aw * d2 + cw * mj2.w);
        }
    }
}

// ---------------------------------------------------------------------------
// k_mix (R12 structure + zero-restoring fold): fold deltas AND zero dq/dmu
// (replaces the per-block memsets); mu@Wv with running norm^2 and V.W dot in
// registers; mixing MLP; gated update. 8 atoms/CTA, 128 threads, 1 col/thr.
// ---------------------------------------------------------------------------
__global__ void __launch_bounds__(128) k_mix(
    float* __restrict__ q, float* __restrict__ mu,
    float* __restrict__ dq, float* __restrict__ dmu,
    const float* __restrict__ Wv,                                  // [128][256]
    const float* __restrict__ mW1, const float* __restrict__ mb1,  // [256][128]
    const float* __restrict__ mW2, const float* __restrict__ mb2)  // [128][384]
{
    __shared__ __align__(16) float qs[TMX * FDIM];
    __shared__ __align__(16) float mus[TMX * 384];
    __shared__ __align__(16) float mws[TMX * 384];
    __shared__ __align__(16) float ns[TMX * FDIM];
    __shared__ __align__(16) float hs[TMX * FDIM];

    const int tid = threadIdx.x;
    const int atom0 = blockIdx.x * TMX;
    const int f = tid;

    // fold segment sums into smem; zero dq/dmu behind us
    {
        const float4 z4 = make_float4(0.f, 0.f, 0.f, 0.f);
        const float4* sq = (const float4*)(q + atom0 * FDIM);
        float4* sdq = (float4*)(dq + atom0 * FDIM);
        float4* dst = (float4*)qs;
        for (int c = tid; c < TMX * 32; c += 128) {
            float4 a = sq[c], b = sdq[c];
            dst[c] = make_float4(a.x + b.x, a.y + b.y, a.z + b.z, a.w + b.w);
            sdq[c] = z4;
        }
        const float4* sm = (const float4*)(mu + atom0 * 384);
        float4* sdm = (float4*)(dmu + atom0 * 384);
        float4* dstm = (float4*)mus;
        for (int c = tid; c < TMX * 96; c += 128) {
            float4 a = sm[c], b = sdm[c];
            dstm[c] = make_float4(a.x + b.x, a.y + b.y, a.z + b.z, a.w + b.w);
            sdm[c] = z4;
        }
    }
    __syncthreads();

    const float4* mus4 = (const float4*)mus;
    float nsq[TMX], dot[TMX];
#pragma unroll
    for (int a = 0; a < TMX; a++) { nsq[a] = 0.f; dot[a] = 0.f; }

#pragma unroll 1
    for (int d = 0; d < 3; d++) {
        float accV[TMX], accW[TMX];
#pragma unroll
        for (int a = 0; a < TMX; a++) { accV[a] = 0.f; accW[a] = 0.f; }
#pragma unroll 2
        for (int kp = 0; kp < 32; kp++) {
            float wv[4], ww[4];
#pragma unroll
            for (int t = 0; t < 4; t++) {
                wv[t] = Wv[(4 * kp + t) * 256 + f];
                ww[t] = Wv[(4 * kp + t) * 256 + FDIM + f];
            }
#pragma unroll
            for (int a = 0; a < TMX; a++) {
                const float4 m = mus4[a * 96 + d * 32 + kp];
                accV[a] += m.x * wv[0] + m.y * wv[1] + m.z * wv[2] + m.w * wv[3];
                accW[a] += m.x * ww[0] + m.y * ww[1] + m.z * ww[2] + m.w * ww[3];
            }
        }
#pragma unroll
        for (int a = 0; a < TMX; a++) {
            mws[a * 384 + d * FDIM + f] = accW[a];
            nsq[a] += accV[a] * accV[a];
            dot[a] += accV[a] * accW[a];
        }
    }
#pragma unroll
    for (int a = 0; a < TMX; a++) ns[a * FDIM + f] = sqrtf(nsq[a] + 1e-8f);
    __syncthreads();

    {
        const float4* qs4 = (const float4*)qs;
        const float4* ns4 = (const float4*)ns;
        float acc[TMX];
#pragma unroll
        for (int a = 0; a < TMX; a++) acc[a] = 0.f;
#pragma unroll 2
        for (int kp = 0; kp < 32; kp++) {
            float w[4];
#pragma unroll
            for (int t = 0; t < 4; t++) w[t] = mW1[(4 * kp + t) * FDIM + f];
#pragma unroll
            for (int a = 0; a < TMX; a++) {
                const float4 v = qs4[a * 32 + kp];
                acc[a] += v.x * w[0] + v.y * w[1] + v.z * w[2] + v.w * w[3];
            }
        }
#pragma unroll 2
        for (int kp = 0; kp < 32; kp++) {
            float w[4];
#pragma unroll
            for (int t = 0; t < 4; t++) w[t] = mW1[(FDIM + 4 * kp + t) * FDIM + f];
#pragma unroll
            for (int a = 0; a < TMX; a++) {
                const float4 v = ns4[a * 32 + kp];
                acc[a] += v.x * w[0] + v.y * w[1] + v.z * w[2] + v.w * w[3];
            }
        }
        const float bb = mb1[f];
#pragma unroll
        for (int a = 0; a < TMX; a++) hs[a * FDIM + f] = silu(acc[a] + bb);
    }
    __syncthreads();

    {
        const float4* hs4 = (const float4*)hs;
        float accA[TMX], accB[TMX], accC[TMX];
#pragma unroll
        for (int a = 0; a < TMX; a++) { accA[a] = 0.f; accB[a] = 0.f; accC[a] = 0.f; }
#pragma unroll 2
        for (int kp = 0; kp < 32; kp++) {
            float wa[4], wb[4], wc[4];
#pragma unroll
            for (int t = 0; t < 4; t++) {
                wa[t] = mW2[(4 * kp + t) * 384 + f];
                wb[t] = mW2[(4 * kp + t) * 384 + FDIM + f];
                wc[t] = mW2[(4 * kp + t) * 384 + 2 * FDIM + f];
            }
#pragma unroll
            for (int a = 0; a < TMX; a++) {
                const float4 v = hs4[a * 32 + kp];
                accA[a] += v.x * wa[0] + v.y * wa[1] + v.z * wa[2] + v.w * wa[3];
                accB[a] += v.x * wb[0] + v.y * wb[1] + v.z * wb[2] + v.w * wb[3];
                accC[a] += v.x * wc[0] + v.y * wc[1] + v.z * wc[2] + v.w * wc[3];
            }
        }
        const float bA = mb2[f], bB = mb2[FDIM + f], bC = mb2[2 * FDIM + f];
#pragma unroll
        for (int a = 0; a < TMX; a++) {
            const float yA = accA[a] + bA;
            const float yB = accB[a] + bB;
            const float yC = accC[a] + bC;
            q[(atom0 + a) * FDIM + f] = qs[a * FDIM + f] + yA + yC * dot[a];
#pragma unroll
            for (int d = 0; d < 3; d++)
                mu[(atom0 + a) * 384 + d * FDIM + f] =
                    mus[a * 384 + d * FDIM + f] + yB * mws[a * 384 + d * FDIM + f];
        }
    }
}

// ---------------------------------------------------------------------------
extern "C" void kernel_launch(void* const* d_in, const int* in_sizes, int n_in,
                              void* d_out, int out_size)
{
    const float* features = (const float*)d_in[0];
    const float* distances = (const float*)d_in[1];
    const float* vectors = (const float*)d_in[2];
    const float* cutoffs = (const float*)d_in[3];
    const float* rbfs = (const float*)d_in[4];
    const float* filter_W = (const float*)d_in[5];
    const float* filter_b = (const float*)d_in[6];
    const float* int_W1 = (const float*)d_in[7];
    const float* int_b1 = (const float*)d_in[8];
    const float* int_W2 = (const float*)d_in[9];
    const float* int_b2 = (const float*)d_in[10];
    const float* mix_Wv = (const float*)d_in[11];
    const float* mix_W1 = (const float*)d_in[12];
    const float* mix_b1 = (const float*)d_in[13];
    const float* mix_W2 = (const float*)d_in[14];
    const float* mix_b2 = (const float*)d_in[15];
    const int* idx_i = (const int*)d_in[16];
    const int* idx_j = (const int*)d_in[17];

    float* q = (float*)d_out;            // [NA,128]
    float* mu = q + NA * FDIM;           // [NA,3,128]

    float *xbuf, *dqbuf, *dmubuf;
    cudaGetSymbolAddress((void**)&xbuf, g_x);
    cudaGetSymbolAddress((void**)&dqbuf, g_dq);
    cudaGetSymbolAddress((void**)&dmubuf, g_dmu);

    cudaMemcpyAsync(q, features, NA * FDIM * sizeof(float), cudaMemcpyDeviceToDevice);
    cudaMemsetAsync(mu, 0, NA * 384 * sizeof(float));

    for (int b = 0; b < NB; b++) {
        k_x<<<NA / TMX, 128>>>(q,
                               int_W1 + b * FDIM * FDIM, int_b1 + b * FDIM,
                               int_W2 + b * FDIM * 384, int_b2 + b * 384,
                               xbuf);
        k_pairs<<<2048, 128>>>(xbuf, mu, distances, vectors, cutoffs, rbfs,
                               filter_W + b * 384, filter_b + b * 384,
                               idx_i, idx_j, dqbuf, dmubuf);
        k_mix<<<NA / TMX, 128>>>(q, mu, dqbuf, dmubuf,
                                 mix_Wv + b * FDIM * 256,
                                 mix_W1 + b * 256 * FDIM, mix_b1 + b * FDIM,
                                 mix_W2 + b * FDIM * 384, mix_b2 + b * 384);
    }
}